// round 4
// baseline (speedup 1.0000x reference)
#include <cuda_runtime.h>

// GeneratorCell: B=128, M=32 queue rows, N=64 strokes, K=2048 stroke length
#define Bn 128
#define Mn 32
#define Nn 64
#define Kn 2048
#define NT 384                     // 12 warps: 256 conv + 128 staging; 352 active in FIR
#define Cn 6                       // consecutive p's per FIR thread; 352*6 = 2112 = N + M*N
#define PAD 64
#define EMB_SZ (PAD + Kn + PAD)    // zero-padded emb => branch-free inner loop

typedef unsigned long long ull;

__device__ __forceinline__ float sigmoidf_(float x) { return 1.0f / (1.0f + __expf(-x)); }

__device__ __forceinline__ ull pack2(float x, float y) {
    ull r; asm("mov.b64 %0, {%1,%2};" : "=l"(r) : "f"(x), "f"(y)); return r;
}
__device__ __forceinline__ void unpack2(ull v, float& x, float& y) {
    asm("mov.b64 {%0,%1}, %2;" : "=f"(x), "=f"(y) : "l"(v));
}
// packed f32x2 FMA (sm_100+): d = a*b + c per 32-bit lane
__device__ __forceinline__ ull ffma2(ull a, ull b, ull c) {
    ull d; asm("fma.rn.f32x2 %0, %1, %2, %3;" : "=l"(d) : "l"(a), "l"(b), "l"(c)); return d;
}

__global__ __launch_bounds__(NT) void gen_cell_kernel(
    const float* __restrict__ qt1,      // [B, M, N, 2]
    const float* __restrict__ ht1,      // [B, N, 2]
    const float* __restrict__ zt,       // [B, N]
    const float* __restrict__ alpha_t,  // [B, N]
    const float* __restrict__ conv_w,   // [2, 2, M+1, 1]
    const float* __restrict__ conv_b,   // [2]
    const float* __restrict__ W_xr, const float* __restrict__ W_hr, const float* __restrict__ b_r,
    const float* __restrict__ W_xu, const float* __restrict__ W_hu, const float* __restrict__ b_u,
    const float* __restrict__ W_xn, const float* __restrict__ W_hn, const float* __restrict__ b_n,
    const float* __restrict__ lin_w,    // [N, 2N]
    const float* __restrict__ lin_b,    // [N]
    const float* __restrict__ W_emb,    // [K, 2]
    float* __restrict__ out)            // st [B,N,2] | qt [B,M,N,2] | ht [B,N,2]
{
    __shared__ float  s_ex[EMB_SZ];     // emb channel x, zero-padded
    __shared__ float  s_ey[EMB_SZ];     // emb channel y, zero-padded
    __shared__ float2 s_part[4 * Nn];   // conv partial sums [group][n] -> (h0, h1)
    __shared__ ull    s_coef2[Nn];      // (coef, coef) packed f32x2
    __shared__ float  s_ht[2 * Nn];

    const int b   = blockIdx.x;
    const int tid = threadIdx.x;
    const float*  q  = qt1 + (size_t)b * Mn * Nn * 2;
    const float2* qf = (const float2*)q;

    // ================= phase 0: conv partials (tid<256) || emb staging (tid>=256) =====
    if (tid < 256) {
        const int n = tid & 63;          // stroke
        const int g = tid >> 6;          // tap group: 8 taps each
        const int h0i = g * 8;
        float p0x = 0.f, p0y = 0.f, p1x = 0.f, p1y = 0.f;  // dual chains per out-channel
        #pragma unroll
        for (int k = 0; k < 8; k += 2) {
            const int ha = h0i + k, hb = h0i + k + 1;
            float2 va = qf[ha * Nn + n];
            float2 vb = qf[hb * Nn + n];
            p0x = fmaf(va.x, conv_w[ha],      fmaf(va.y, conv_w[33 + ha], p0x));
            p1x = fmaf(va.x, conv_w[66 + ha], fmaf(va.y, conv_w[99 + ha], p1x));
            p0y = fmaf(vb.x, conv_w[hb],      fmaf(vb.y, conv_w[33 + hb], p0y));
            p1y = fmaf(vb.x, conv_w[66 + hb], fmaf(vb.y, conv_w[99 + hb], p1y));
        }
        s_part[g * Nn + n] = make_float2(p0x + p0y, p1x + p1y);
    } else {
        const int t2 = tid - 256;        // 128 staging threads
        if (t2 < PAD) {
            s_ex[t2] = 0.0f; s_ey[t2] = 0.0f;
            s_ex[PAD + Kn + t2] = 0.0f; s_ey[PAD + Kn + t2] = 0.0f;
        }
        const float4* we4 = (const float4*)W_emb;   // 2 emb entries per float4
        #pragma unroll
        for (int i = t2; i < Kn / 2; i += 128) {
            float4 w = we4[i];
            s_ex[PAD + 2 * i]     = w.x; s_ey[PAD + 2 * i]     = w.y;
            s_ex[PAD + 2 * i + 1] = w.z; s_ey[PAD + 2 * i + 1] = w.w;
        }
    }
    __syncthreads();

    // ================= phase 1: GRU + intensity (tid<64 only; short tail) =============
    if (tid < 64) {
        const int n = tid;
        const float2 hv = ((const float2*)ht1)[b * Nn + n];
        float2 pa = s_part[n],            pb = s_part[Nn + n];
        float2 pc = s_part[2 * Nn + n],   pd = s_part[3 * Nn + n];
        float h0 = (pa.x + pb.x) + (pc.x + pd.x) + conv_b[0]
                 + hv.x * conv_w[32] + hv.y * conv_w[65];
        float h1 = (pa.y + pb.y) + (pc.y + pd.y) + conv_b[1]
                 + hv.x * conv_w[98] + hv.y * conv_w[131];

        const float x0 = zt[b * Nn + n];
        const float x1 = alpha_t[b * Nn + n];

        float r0 = sigmoidf_(fmaf(x0, W_xr[0], fmaf(x1, W_xr[2], fmaf(h0, W_hr[0], fmaf(h1, W_hr[2], b_r[0])))));
        float r1 = sigmoidf_(fmaf(x0, W_xr[1], fmaf(x1, W_xr[3], fmaf(h0, W_hr[1], fmaf(h1, W_hr[3], b_r[1])))));
        float u0 = sigmoidf_(fmaf(x0, W_xu[0], fmaf(x1, W_xu[2], fmaf(h0, W_hu[0], fmaf(h1, W_hu[2], b_u[0])))));
        float u1 = sigmoidf_(fmaf(x0, W_xu[1], fmaf(x1, W_xu[3], fmaf(h0, W_hu[1], fmaf(h1, W_hu[3], b_u[1])))));

        const float rh0 = r0 * h0, rh1 = r1 * h1;
        float nt0 = tanhf(fmaf(x0, W_xn[0], fmaf(x1, W_xn[2], fmaf(rh0, W_hn[0], fmaf(rh1, W_hn[2], b_n[0])))));
        float nt1 = tanhf(fmaf(x0, W_xn[1], fmaf(x1, W_xn[3], fmaf(rh0, W_hn[1], fmaf(rh1, W_hn[3], b_n[1])))));

        const float hn0 = u0 * hv.x + (1.0f - u0) * nt0;
        const float hn1 = u1 * hv.y + (1.0f - u1) * nt1;

        s_ht[2 * n + 0] = hn0;
        s_ht[2 * n + 1] = hn1;

        const size_t off_ht = (size_t)Bn * Nn * 2 + (size_t)Bn * Mn * Nn * 2;
        out[off_ht + ((size_t)b * Nn + n) * 2 + 0] = hn0;
        out[off_ht + ((size_t)b * Nn + n) * 2 + 1] = hn1;
    }
    __syncthreads();

    if (tid < 64) {
        const int n = tid;
        float a0 = lin_b[n], a1 = 0.0f, a2 = 0.0f, a3 = 0.0f;
        const float* lw = lin_w + (size_t)n * 2 * Nn;
        #pragma unroll 8
        for (int j = 0; j < 2 * Nn; j += 4) {
            a0 = fmaf(s_ht[j + 0], lw[j + 0], a0);
            a1 = fmaf(s_ht[j + 1], lw[j + 1], a1);
            a2 = fmaf(s_ht[j + 2], lw[j + 2], a2);
            a3 = fmaf(s_ht[j + 3], lw[j + 3], a3);
        }
        const float c = ((a0 + a1) + (a2 + a3)) * alpha_t[b * Nn + n];
        s_coef2[n] = pack2(c, c);
    }
    __syncthreads();

    // ================= phase 3: FIR overlap-add, C=6 sliding window ====================
    if (tid < 352) {
        const int p0 = tid * Cn;
        ull acc[Cn], w[Cn];
        #pragma unroll
        for (int i = 0; i < Cn; i++) {
            w[i] = pack2(s_ex[PAD + p0 + i], s_ey[PAD + p0 + i]);
            acc[i] = 0ULL;
        }
        #pragma unroll
        for (int n = 0; n < Nn; n++) {
            const ull c2 = s_coef2[n];                // warp-uniform broadcast
            #pragma unroll
            for (int i = 0; i < Cn; i++) acc[i] = ffma2(c2, w[i], acc[i]);
            #pragma unroll
            for (int i = Cn - 1; i > 0; i--) w[i] = w[i - 1];   // renaming (full unroll)
            w[0] = pack2(s_ex[PAD + p0 - n - 1], s_ey[PAD + p0 - n - 1]);
        }

        // ---- output assembly ----
        float2* st_out = (float2*)out + (size_t)b * Nn;
        float2* qt_out = (float2*)(out + (size_t)Bn * Nn * 2) + (size_t)b * Mn * Nn;
        #pragma unroll
        for (int i = 0; i < Cn; i++) {
            const int p = p0 + i;
            float fx, fy; unpack2(acc[i], fx, fy);
            float2 qv = make_float2(0.0f, 0.0f);
            if (p < Mn * Nn) qv = qf[p];              // q_shift[j] = q_flat[j+N] = q_flat[p]
            float2 r = make_float2(qv.x + fx, qv.y + fy);
            if (p < Nn) st_out[p] = r;                // st = q_row0 + f[:N]
            else        qt_out[p - Nn] = r;           // qt = q_shift + tail
        }
    }
}

extern "C" void kernel_launch(void* const* d_in, const int* in_sizes, int n_in,
                              void* d_out, int out_size) {
    const float* qt1     = (const float*)d_in[0];
    const float* ht1     = (const float*)d_in[1];
    const float* zt      = (const float*)d_in[2];
    const float* alpha_t = (const float*)d_in[3];
    const float* conv_w  = (const float*)d_in[4];
    const float* conv_b  = (const float*)d_in[5];
    const float* W_xr    = (const float*)d_in[6];
    const float* W_hr    = (const float*)d_in[7];
    const float* b_r     = (const float*)d_in[8];
    const float* W_xu    = (const float*)d_in[9];
    const float* W_hu    = (const float*)d_in[10];
    const float* b_u     = (const float*)d_in[11];
    const float* W_xn    = (const float*)d_in[12];
    const float* W_hn    = (const float*)d_in[13];
    const float* b_n     = (const float*)d_in[14];
    const float* lin_w   = (const float*)d_in[15];
    const float* lin_b   = (const float*)d_in[16];
    const float* W_emb   = (const float*)d_in[17];

    gen_cell_kernel<<<Bn, NT>>>(qt1, ht1, zt, alpha_t, conv_w, conv_b,
                                W_xr, W_hr, b_r, W_xu, W_hu, b_u,
                                W_xn, W_hn, b_n, lin_w, lin_b, W_emb,
                                (float*)d_out);
}

// round 5
// speedup vs baseline: 2.1701x; 2.1701x over previous
#include <cuda_runtime.h>

// GeneratorCell: B=128, M=32 queue rows, N=64 strokes, K=2048 stroke length
#define Bn 128
#define Mn 32
#define Nn 64
#define Kn 2048
#define NT 192                     // 6 warps
#define Cn 11                      // consecutive p's per thread; 192*11 = 2112 = N + M*N
#define PAD 72                     // bottom zero pad (>=66 for prefetch reach); top pad 64
#define EMB_SZ (PAD + Kn + 64)

typedef unsigned long long ull;

__device__ __forceinline__ float sigmoidf_(float x) { return 1.0f / (1.0f + __expf(-x)); }

__device__ __forceinline__ ull pack2(float x, float y) {
    ull r; asm("mov.b64 %0, {%1,%2};" : "=l"(r) : "f"(x), "f"(y)); return r;
}
__device__ __forceinline__ void unpack2(ull v, float& x, float& y) {
    asm("mov.b64 {%0,%1}, %2;" : "=f"(x), "=f"(y) : "l"(v));
}
// packed f32x2 FMA (sm_100+): d = a*b + c per 32-bit lane
__device__ __forceinline__ ull ffma2(ull a, ull b, ull c) {
    ull d; asm("fma.rn.f32x2 %0, %1, %2, %3;" : "=l"(d) : "l"(a), "l"(b), "l"(c)); return d;
}

__global__ __launch_bounds__(NT) void gen_cell_kernel(
    const float* __restrict__ qt1,      // [B, M, N, 2]
    const float* __restrict__ ht1,      // [B, N, 2]
    const float* __restrict__ zt,       // [B, N]
    const float* __restrict__ alpha_t,  // [B, N]
    const float* __restrict__ conv_w,   // [2, 2, M+1, 1]
    const float* __restrict__ conv_b,   // [2]
    const float* __restrict__ W_xr, const float* __restrict__ W_hr, const float* __restrict__ b_r,
    const float* __restrict__ W_xu, const float* __restrict__ W_hu, const float* __restrict__ b_u,
    const float* __restrict__ W_xn, const float* __restrict__ W_hn, const float* __restrict__ b_n,
    const float* __restrict__ lin_w,    // [N, 2N]
    const float* __restrict__ lin_b,    // [N]
    const float* __restrict__ W_emb,    // [K, 2]
    float* __restrict__ out)            // st [B,N,2] | qt [B,M,N,2] | ht [B,N,2]
{
    __shared__ __align__(16) float s_ex[EMB_SZ];   // emb channel x, zero-padded
    __shared__ __align__(16) float s_ey[EMB_SZ];   // emb channel y, zero-padded
    __shared__ float2 s_part[3 * Nn];              // conv partials [group][n] -> (h0, h1)
    __shared__ ull    s_coef2[Nn];                 // (coef, coef) packed f32x2
    __shared__ __align__(16) float s_ht[2 * Nn];

    const int b    = blockIdx.x;
    const int tid  = threadIdx.x;
    const int lane = tid & 31;
    const int wrp  = tid >> 5;
    const float2* qf = (const float2*)(qt1 + (size_t)b * Mn * Nn * 2);

    // ============ phase 0: emb staging LDGs + conv partials, all 192 threads ============
    {
        const int n = tid & 63;          // stroke
        const int g = tid >> 6;          // tap group (0..2), 11 taps each; 3*11=33 = M+1

        // -- issue all W_emb staging loads first (latency overlaps with conv loads) --
        const float4* we4 = (const float4*)W_emb;   // 1024 float4 total
        float4 e0 = we4[tid],       e1 = we4[tid + 192], e2 = we4[tid + 384];
        float4 e3 = we4[tid + 576], e4 = we4[tid + 768];
        float4 e5 = make_float4(0.f, 0.f, 0.f, 0.f);
        if (tid < 64) e5 = we4[tid + 960];

        // -- conv input loads (tap h = g*11+k; tap 32 is the ht1 row) --
        float2 v[11];
        #pragma unroll
        for (int k = 0; k < 11; k++) {
            const int h = g * 11 + k;
            v[k] = (h < 32) ? qf[h * Nn + n] : ((const float2*)ht1)[b * Nn + n];
        }

        // -- zero the emb pads --
        if (tid < PAD) { s_ex[tid] = 0.0f; s_ey[tid] = 0.0f; }
        if (tid < 64)  { s_ex[PAD + Kn + tid] = 0.0f; s_ey[PAD + Kn + tid] = 0.0f; }

        // -- store staged emb, SoA split (float2 stores; PAD even => 8B aligned) --
        float2* ex2 = (float2*)(s_ex + PAD);
        float2* ey2 = (float2*)(s_ey + PAD);
        ex2[tid]       = make_float2(e0.x, e0.z);  ey2[tid]       = make_float2(e0.y, e0.w);
        ex2[tid + 192] = make_float2(e1.x, e1.z);  ey2[tid + 192] = make_float2(e1.y, e1.w);
        ex2[tid + 384] = make_float2(e2.x, e2.z);  ey2[tid + 384] = make_float2(e2.y, e2.w);
        ex2[tid + 576] = make_float2(e3.x, e3.z);  ey2[tid + 576] = make_float2(e3.y, e3.w);
        ex2[tid + 768] = make_float2(e4.x, e4.z);  ey2[tid + 768] = make_float2(e4.y, e4.w);
        if (tid < 64) {
            ex2[tid + 960] = make_float2(e5.x, e5.z);
            ey2[tid + 960] = make_float2(e5.y, e5.w);
        }

        // -- conv partial sums, dual chains --
        float p0a = 0.f, p0b = 0.f, p1a = 0.f, p1b = 0.f;
        #pragma unroll
        for (int k = 0; k < 11; k++) {
            const int h = g * 11 + k;
            const float wa = conv_w[h], wb = conv_w[33 + h];
            const float wc = conv_w[66 + h], wd = conv_w[99 + h];
            if (k & 1) {
                p0b = fmaf(v[k].x, wa, fmaf(v[k].y, wb, p0b));
                p1b = fmaf(v[k].x, wc, fmaf(v[k].y, wd, p1b));
            } else {
                p0a = fmaf(v[k].x, wa, fmaf(v[k].y, wb, p0a));
                p1a = fmaf(v[k].x, wc, fmaf(v[k].y, wd, p1a));
            }
        }
        s_part[g * Nn + n] = make_float2(p0a + p0b, p1a + p1b);
    }
    __syncthreads();

    // ============ phase 1: GRU per stroke (tid<64; short) ============
    if (tid < 64) {
        const int n = tid;
        const float2 hv = ((const float2*)ht1)[b * Nn + n];   // L1 hit
        const float2 pa = s_part[n], pb = s_part[Nn + n], pc = s_part[2 * Nn + n];
        const float h0 = (pa.x + pb.x) + pc.x + conv_b[0];    // ht1 tap already in pc
        const float h1 = (pa.y + pb.y) + pc.y + conv_b[1];

        const float x0 = zt[b * Nn + n];
        const float x1 = alpha_t[b * Nn + n];

        float r0 = sigmoidf_(fmaf(x0, W_xr[0], fmaf(x1, W_xr[2], fmaf(h0, W_hr[0], fmaf(h1, W_hr[2], b_r[0])))));
        float r1 = sigmoidf_(fmaf(x0, W_xr[1], fmaf(x1, W_xr[3], fmaf(h0, W_hr[1], fmaf(h1, W_hr[3], b_r[1])))));
        float u0 = sigmoidf_(fmaf(x0, W_xu[0], fmaf(x1, W_xu[2], fmaf(h0, W_hu[0], fmaf(h1, W_hu[2], b_u[0])))));
        float u1 = sigmoidf_(fmaf(x0, W_xu[1], fmaf(x1, W_xu[3], fmaf(h0, W_hu[1], fmaf(h1, W_hu[3], b_u[1])))));

        const float rh0 = r0 * h0, rh1 = r1 * h1;
        float nt0 = tanhf(fmaf(x0, W_xn[0], fmaf(x1, W_xn[2], fmaf(rh0, W_hn[0], fmaf(rh1, W_hn[2], b_n[0])))));
        float nt1 = tanhf(fmaf(x0, W_xn[1], fmaf(x1, W_xn[3], fmaf(rh0, W_hn[1], fmaf(rh1, W_hn[3], b_n[1])))));

        const float hn0 = u0 * hv.x + (1.0f - u0) * nt0;
        const float hn1 = u1 * hv.y + (1.0f - u1) * nt1;

        s_ht[2 * n + 0] = hn0;
        s_ht[2 * n + 1] = hn1;

        const size_t off_ht = (size_t)Bn * Nn * 2 + (size_t)Bn * Mn * Nn * 2;
        out[off_ht + ((size_t)b * Nn + n) * 2 + 0] = hn0;
        out[off_ht + ((size_t)b * Nn + n) * 2 + 1] = hn1;
    }
    __syncthreads();

    // ============ phase 2: coef matvec, warp-per-rows with coalesced loads ============
    {
        const float4 ht4 = ((const float4*)s_ht)[lane];       // whole ht vector, per lane slice
        const float4* lw4 = (const float4*)lin_w;             // [64 rows][32 float4]
        #pragma unroll
        for (int k = 0; k < 11; k++) {
            const int row = wrp * 11 + k;                     // 6 warps x 11 >= 64
            if (row < Nn) {
                const float4 lv = lw4[row * 32 + lane];       // coalesced 512B per warp
                float d = fmaf(lv.x, ht4.x, fmaf(lv.y, ht4.y, fmaf(lv.z, ht4.z, lv.w * ht4.w)));
                d += __shfl_xor_sync(0xffffffffu, d, 16);
                d += __shfl_xor_sync(0xffffffffu, d, 8);
                d += __shfl_xor_sync(0xffffffffu, d, 4);
                d += __shfl_xor_sync(0xffffffffu, d, 2);
                d += __shfl_xor_sync(0xffffffffu, d, 1);
                if (lane == 0) {
                    const float c = (d + lin_b[row]) * alpha_t[b * Nn + row];
                    s_coef2[row] = pack2(c, c);
                }
            }
        }
    }
    __syncthreads();

    // ============ phase 3: FIR overlap-add, C=11 sliding window + depth-1 prefetch ======
    const int p0 = tid * Cn;
    ull acc[Cn], w[Cn];
    #pragma unroll
    for (int i = 0; i < Cn; i++) {
        w[i] = pack2(s_ex[PAD + p0 + i], s_ey[PAD + p0 + i]);
        acc[i] = 0ULL;
    }
    float nx = s_ex[PAD + p0 - 1], ny = s_ey[PAD + p0 - 1];
    #pragma unroll
    for (int n = 0; n < Nn; n++) {
        const ull c2 = s_coef2[n];                 // warp-uniform broadcast
        #pragma unroll
        for (int i = 0; i < Cn; i++) acc[i] = ffma2(c2, w[i], acc[i]);
        #pragma unroll
        for (int i = Cn - 1; i > 0; i--) w[i] = w[i - 1];   // register renaming (full unroll)
        w[0] = pack2(nx, ny);
        nx = s_ex[PAD + p0 - n - 2];               // prefetch next (min idx = PAD-65 = 7 >= 0)
        ny = s_ey[PAD + p0 - n - 2];               // stride 11 words: conflict-free
    }

    // ============ output assembly ============
    float2* st_out = (float2*)out + (size_t)b * Nn;
    float2* qt_out = (float2*)(out + (size_t)Bn * Nn * 2) + (size_t)b * Mn * Nn;
    #pragma unroll
    for (int i = 0; i < Cn; i++) {
        const int p = p0 + i;
        float fx, fy; unpack2(acc[i], fx, fy);
        float2 qv = make_float2(0.0f, 0.0f);
        if (p < Mn * Nn) qv = qf[p];               // q_shift[j] = q_flat[j+N] = q_flat[p]
        float2 r = make_float2(qv.x + fx, qv.y + fy);
        if (p < Nn) st_out[p] = r;                 // st = q_row0 + f[:N]
        else        qt_out[p - Nn] = r;            // qt = q_shift + tail
    }
}

extern "C" void kernel_launch(void* const* d_in, const int* in_sizes, int n_in,
                              void* d_out, int out_size) {
    const float* qt1     = (const float*)d_in[0];
    const float* ht1     = (const float*)d_in[1];
    const float* zt      = (const float*)d_in[2];
    const float* alpha_t = (const float*)d_in[3];
    const float* conv_w  = (const float*)d_in[4];
    const float* conv_b  = (const float*)d_in[5];
    const float* W_xr    = (const float*)d_in[6];
    const float* W_hr    = (const float*)d_in[7];
    const float* b_r     = (const float*)d_in[8];
    const float* W_xu    = (const float*)d_in[9];
    const float* W_hu    = (const float*)d_in[10];
    const float* b_u     = (const float*)d_in[11];
    const float* W_xn    = (const float*)d_in[12];
    const float* W_hn    = (const float*)d_in[13];
    const float* b_n     = (const float*)d_in[14];
    const float* lin_w   = (const float*)d_in[15];
    const float* lin_b   = (const float*)d_in[16];
    const float* W_emb   = (const float*)d_in[17];

    gen_cell_kernel<<<Bn, NT>>>(qt1, ht1, zt, alpha_t, conv_w, conv_b,
                                W_xr, W_hr, b_r, W_xu, W_hu, b_u,
                                W_xn, W_hn, b_n, lin_w, lin_b, W_emb,
                                (float*)d_out);
}